// round 3
// baseline (speedup 1.0000x reference)
#include <cuda_runtime.h>
#include <math.h>

// ---------------------------------------------------------------------------
// ASSR reconstruction loss — ONE fused kernel, single pass over pred/target.
//   pix  = mean|pred - target|                  (32,3,512,512)
//   lr   = mean|bicubicAA_down4(pred) - lr_ref| (32,3,128,128)
//   out  = { pix + 0.1*lr, pix, lr, lr, 0 }
//
// Bicubic antialias (a=-0.75), scale=4, align_corners=False: every output
// uses the same 16-tap window (raw sum = 4.0 exactly); border replicate
// folds clamped taps into rows/cols 0 and 511 (closed-form sums WA..WD).
//
// Each block owns (bc, 32 contiguous output rows): vertical polyphase FIR
// with rolling accumulators across two 16-row chunks (16-row smem buffer,
// 12.5% row halo), horizontal FIR + |.-lr_ref| after each chunk.
// Grid 384 blocks, 512 threads, 4 blocks/SM -> single wave, 100% occupancy.
// Last finishing block reduces all per-block partials and writes the output.
// ---------------------------------------------------------------------------

#define HW       512
#define OUTHW    128
#define NBC      96            // 32 batch * 3 channels
#define CHAIN    32            // output rows per block
#define SPLITS   (OUTHW / CHAIN) // 4
#define BUF      16            // smem row buffer (one chunk)
#define THREADS  512
#define NBLOCKS  (SPLITS * NBC)  // 384

// normalized taps (raw cubic values are dyadic; raw window sum = 4.0 exactly)
#define WT0 (-0.0025634765625f)
#define WT1 (-0.0164794921875f)
#define WT2 (-0.0274658203125f)
#define WT3 (-0.0179443359375f)
#define WT4 ( 0.0286865234375f)
#define WT5 ( 0.1065673828125f)
#define WT6 ( 0.1873779296875f)
#define WT7 ( 0.2418212890625f)
// border-folded sums (replicate clamp)
#define WA  ( 0.2581787109375f)  // sum wt[0..6]
#define WB  (-0.0465087890625f)  // sum wt[0..2]
#define WC  WB                   // sum wt[13..15] (symmetry)
#define WD  WA                   // sum wt[9..15]

__constant__ float c_wt[16] = {WT0,WT1,WT2,WT3,WT4,WT5,WT6,WT7,
                               WT7,WT6,WT5,WT4,WT3,WT2,WT1,WT0};

// per-block partial sums; every block overwrites its slot each launch
__device__ double g_pp[NBLOCKS];
__device__ double g_pl[NBLOCKS];
__device__ unsigned int g_count;   // zero-init; last block resets to 0

__global__ __launch_bounds__(THREADS)
void assr_fused_kernel(const float* __restrict__ pred,
                       const float* __restrict__ tgt,
                       const float* __restrict__ lrr,
                       float* __restrict__ out, int out_size)
{
    __shared__ float  vrows[BUF * HW];   // 32 KB chunk buffer
    __shared__ float  red[32];
    __shared__ double dred[32];
    __shared__ unsigned sh_last;

    const int w   = threadIdx.x;         // column 0..511
    const int s   = blockIdx.x;          // 0..3
    const int bc  = blockIdx.y;          // 0..95
    const int oh0 = CHAIN * s;

    const float* P = pred + (size_t)bc * (HW * HW);
    const float* T = tgt  + (size_t)bc * (HW * HW);

    // rolling vertical accumulators: A[i] <-> output row k+(i-2) for group k
    float A0 = 0.f, A1 = 0.f, A2 = 0.f, A3 = 0.f, A4 = 0.f;
    float pixs = 0.f, lrs = 0.f;

    const int ow = w & (OUTHW - 1);
    const int r0 = w >> 7;               // 0..3
    const bool interior = (ow >= 2) && (ow < OUTHW - 2);

    #pragma unroll
    for (int chunk = 0; chunk < 2; ++chunk) {
        const int kkA = chunk ? 20 : 0;
        const int kkB = chunk ? 36 : 20;

        // ---- vertical polyphase FIR + pix reduction over this chunk ----
        #pragma unroll
        for (int kk = kkA; kk < kkB; ++kk) {
            const int k  = oh0 - 2 + kk;
            const int hb = 4 * k;
            if (hb >= 0 && hb < HW) {
                const float* pp = P + (size_t)hb * HW + w;
                const float p0 = pp[0];
                const float p1 = pp[HW];
                const float p2 = pp[2 * HW];
                const float p3 = pp[3 * HW];
                if (kk >= 2 && kk < 2 + CHAIN) {  // core rows: count pix once
                    const float* tp = T + (size_t)hb * HW + w;
                    pixs += fabsf(p0 - tp[0])      + fabsf(p1 - tp[HW])
                          + fabsf(p2 - tp[2 * HW]) + fabsf(p3 - tp[3 * HW]);
                }
                // phase r=0: taps 14,10,6,2 -> oh k-2..k+1
                if (hb == 0) { A2 += WA * p0; A3 += WB * p0; }     // border
                else { A0 += WT1*p0; A1 += WT5*p0; A2 += WT6*p0; A3 += WT2*p0; }
                // phase r=1: taps 15,11,7,3 -> oh k-2..k+1
                A0 += WT0*p1; A1 += WT4*p1; A2 += WT7*p1; A3 += WT3*p1;
                // phase r=2: taps 12,8,4,0  -> oh k-1..k+2
                A1 += WT3*p2; A2 += WT7*p2; A3 += WT4*p2; A4 += WT0*p2;
                // phase r=3: taps 13,9,5,1  -> oh k-1..k+2
                if (hb == HW - 4) { A1 += WC * p3; A2 += WD * p3; } // border
                else { A1 += WT2*p3; A2 += WT6*p3; A3 += WT5*p3; A4 += WT1*p3; }
            }
            // output row oh = k-2 = oh0 + kk - 4 complete after group k
            if (kk >= 4)
                vrows[((kk - 4) & (BUF - 1)) * HW + w] = A0;
            A0 = A1; A1 = A2; A2 = A3; A3 = A4; A4 = 0.f;
        }
        __syncthreads();

        // ---- horizontal FIR from smem + lr reduction for this chunk ----
        const float* lrbase = lrr + (size_t)bc * (OUTHW * OUTHW)
                                  + (size_t)(oh0 + chunk * BUF) * OUTHW + ow;
        if (interior) {
            #pragma unroll
            for (int i = 0; i < BUF / 4; ++i) {
                const int rr = r0 + 4 * i;
                const float4* v =
                    reinterpret_cast<const float4*>(vrows + rr * HW) + (ow - 2);
                const float4 a = v[0], b = v[1], c = v[2], d = v[3], e = v[4];
                float acc = a.z * WT0 + a.w * WT1
                          + b.x * WT2 + b.y * WT3 + b.z * WT4 + b.w * WT5
                          + c.x * WT6 + c.y * WT7 + c.z * WT7 + c.w * WT6
                          + d.x * WT5 + d.y * WT4 + d.z * WT3 + d.w * WT2
                          + e.x * WT1 + e.y * WT0;
                lrs += fabsf(acc - lrbase[rr * OUTHW]);
            }
        } else {
            // border ow in {0,1,126,127}: scalar clamped gather
            for (int i = 0; i < BUF / 4; ++i) {
                const int rr = r0 + 4 * i;
                const float* row = vrows + rr * HW;
                float acc = 0.f;
                #pragma unroll
                for (int tt = 0; tt < 16; ++tt) {
                    int src = 4 * ow - 6 + tt;
                    src = src < 0 ? 0 : (src > HW - 1 ? HW - 1 : src);
                    acc += c_wt[tt] * row[src];
                }
                lrs += fabsf(acc - lrbase[rr * OUTHW]);
            }
        }
        __syncthreads();   // protect vrows before next chunk's writes
    }

    // ---------------- block reduction -> per-block partial slot ------------
    #pragma unroll
    for (int o = 16; o; o >>= 1) {
        pixs += __shfl_xor_sync(0xffffffffu, pixs, o);
        lrs  += __shfl_xor_sync(0xffffffffu, lrs,  o);
    }
    const int wid = w >> 5, lane = w & 31;
    if (lane == 0) { red[wid] = pixs; red[16 + wid] = lrs; }
    __syncthreads();
    if (w == 0) {
        double ps = 0.0, ls = 0.0;
        #pragma unroll
        for (int i = 0; i < THREADS / 32; ++i) {
            ps += (double)red[i];
            ls += (double)red[16 + i];
        }
        const int slot = bc * SPLITS + s;
        g_pp[slot] = ps;
        g_pl[slot] = ls;
        __threadfence();
        const unsigned old = atomicAdd(&g_count, 1u);
        sh_last = (old == NBLOCKS - 1) ? 1u : 0u;
    }
    __syncthreads();

    // ---------------- last block finalizes ---------------------------------
    if (sh_last) {
        double p = 0.0, l = 0.0;
        if (w < NBLOCKS) {       // 384 active loaders
            p = __ldcg(&g_pp[w]);
            l = __ldcg(&g_pl[w]);
        }
        #pragma unroll
        for (int o = 16; o; o >>= 1) {
            p += __shfl_xor_sync(0xffffffffu, p, o);
            l += __shfl_xor_sync(0xffffffffu, l, o);
        }
        if (lane == 0) { dred[wid] = p; dred[16 + wid] = l; }
        __syncthreads();
        if (w == 0) {
            double ps = 0.0, ls = 0.0;
            #pragma unroll
            for (int i = 0; i < THREADS / 32; ++i) {
                ps += dred[i];
                ls += dred[16 + i];
            }
            const double pix     = ps / 25165824.0;   // 32*3*512*512
            const double lr      = ls / 1572864.0;    // 32*3*128*128
            const double consist = lr;                // LAM_LR*lr + 0
            const double total   = pix + 0.1 * consist;
            float vals[5] = {(float)total, (float)pix, (float)consist,
                             (float)lr, 0.f};
            for (int i = 0; i < out_size; ++i)
                out[i] = (i < 5) ? vals[i] : 0.f;
            g_count = 0;          // reset for next launch (deterministic)
        }
    }
}

extern "C" void kernel_launch(void* const* d_in, const int* in_sizes, int n_in,
                              void* d_out, int out_size)
{
    const float* pred = (const float*)d_in[0];
    const float* tgt  = (const float*)d_in[1];
    const float* lrr  = (const float*)d_in[2];
    // d_in[3] (scale) is uniform 4.0 -> static sizes, unused.

    const dim3 grid(SPLITS, NBC);
    assr_fused_kernel<<<grid, THREADS>>>(pred, tgt, lrr,
                                         (float*)d_out, out_size);
}

// round 4
// speedup vs baseline: 1.5734x; 1.5734x over previous
#include <cuda_runtime.h>
#include <math.h>

// ---------------------------------------------------------------------------
// ASSR reconstruction loss — ONE fused kernel, single pass over pred/target.
//   pix  = mean|pred - target|                  (32,3,512,512)
//   lr   = mean|bicubicAA_down4(pred) - lr_ref| (32,3,128,128)
//   out  = { pix + 0.1*lr, pix, lr, lr, 0 }
//
// Bicubic AA (a=-0.75), scale=4, align_corners=False: identical 16-tap
// window everywhere (raw sum = 4.0 exactly); replicate border folds into
// rows/cols 0 and 511 (closed-form sums WA..WD).
//
// Shape chosen for occupancy: 256 thr/block (float2 per thread), <=51 regs
// (launch_bounds 256,5) -> 5 blocks/SM, grid 768 ~ one wave. Hot loop is
// fully branch-free via <FIRST,LAST> template dispatch (compile-time border
// handling) so LDGs front-batch for high MLP.
// ---------------------------------------------------------------------------

#define HW       512
#define OUTHW    128
#define NBC      96             // 32 batch * 3 channels
#define CHAIN    16             // output rows per block
#define SPLITS   8
#define THREADS  256
#define NBLOCKS  (SPLITS * NBC) // 768
#define RS       (HW / 2)       // row stride in float2

// normalized taps (raw cubic values are dyadic; raw window sum = 4.0 exactly)
#define WT0 (-0.0025634765625f)
#define WT1 (-0.0164794921875f)
#define WT2 (-0.0274658203125f)
#define WT3 (-0.0179443359375f)
#define WT4 ( 0.0286865234375f)
#define WT5 ( 0.1065673828125f)
#define WT6 ( 0.1873779296875f)
#define WT7 ( 0.2418212890625f)
// border-folded sums (replicate clamp)
#define WA  ( 0.2581787109375f)  // sum wt[0..6]
#define WB  (-0.0465087890625f)  // sum wt[0..2]
#define WC  WB                   // sum wt[13..15] (symmetry)
#define WD  WA                   // sum wt[9..15]

__constant__ float c_wt[16] = {WT0,WT1,WT2,WT3,WT4,WT5,WT6,WT7,
                               WT7,WT6,WT5,WT4,WT3,WT2,WT1,WT0};

__device__ double g_pp[NBLOCKS];
__device__ double g_pl[NBLOCKS];
__device__ unsigned int g_count;   // zero-init; last block resets to 0

// Vertical polyphase FIR + pix reduction, fully unrolled and branch-free.
// Group k reads input rows 4k..4k+3; output row oh gets groups oh-2..oh+2.
// A[i] <-> output row k+(i-2). FIRST/LAST make all guards compile-time.
template<bool FIRST, bool LAST>
__device__ __forceinline__ void vert_pass(const float2* __restrict__ P2,
                                          const float2* __restrict__ T2,
                                          const int oh0, const int t,
                                          float* __restrict__ vrows,
                                          float& pixs)
{
    float A0x=0.f,A0y=0.f, A1x=0.f,A1y=0.f, A2x=0.f,A2y=0.f,
          A3x=0.f,A3y=0.f, A4x=0.f,A4y=0.f;

    #pragma unroll
    for (int kk = 0; kk < CHAIN + 4; ++kk) {
        const bool valid = (!FIRST || kk >= 2) && (!LAST || kk <= 17);
        if (valid) {
            const int k = oh0 - 2 + kk;
            const float2* pp = P2 + (size_t)(4 * k) * RS;
            const float2 p0 = pp[0];
            const float2 p1 = pp[RS];
            const float2 p2 = pp[2 * RS];
            const float2 p3 = pp[3 * RS];
            if (kk >= 2 && kk < 18) {          // core groups: pix exactly once
                const float2* tp = T2 + (size_t)(4 * k) * RS;
                const float2 t0 = __ldcs(tp);
                const float2 t1 = __ldcs(tp + RS);
                const float2 t2 = __ldcs(tp + 2 * RS);
                const float2 t3 = __ldcs(tp + 3 * RS);
                pixs += fabsf(p0.x - t0.x) + fabsf(p0.y - t0.y)
                      + fabsf(p1.x - t1.x) + fabsf(p1.y - t1.y)
                      + fabsf(p2.x - t2.x) + fabsf(p2.y - t2.y)
                      + fabsf(p3.x - t3.x) + fabsf(p3.y - t3.y);
            }
            // phase r=0 (input row 4k): taps 14,10,6,2 -> oh k-2..k+1
            if (FIRST && kk == 2) {            // hb==0 border fold
                A2x += WA * p0.x; A2y += WA * p0.y;
                A3x += WB * p0.x; A3y += WB * p0.y;
            } else {
                A0x += WT1 * p0.x; A0y += WT1 * p0.y;
                A1x += WT5 * p0.x; A1y += WT5 * p0.y;
                A2x += WT6 * p0.x; A2y += WT6 * p0.y;
                A3x += WT2 * p0.x; A3y += WT2 * p0.y;
            }
            // phase r=1: taps 15,11,7,3 -> oh k-2..k+1
            A0x += WT0 * p1.x; A0y += WT0 * p1.y;
            A1x += WT4 * p1.x; A1y += WT4 * p1.y;
            A2x += WT7 * p1.x; A2y += WT7 * p1.y;
            A3x += WT3 * p1.x; A3y += WT3 * p1.y;
            // phase r=2: taps 12,8,4,0 -> oh k-1..k+2
            A1x += WT3 * p2.x; A1y += WT3 * p2.y;
            A2x += WT7 * p2.x; A2y += WT7 * p2.y;
            A3x += WT4 * p2.x; A3y += WT4 * p2.y;
            A4x += WT0 * p2.x; A4y += WT0 * p2.y;
            // phase r=3: taps 13,9,5,1 -> oh k-1..k+2
            if (LAST && kk == 17) {            // hb==HW-4 border fold
                A1x += WC * p3.x; A1y += WC * p3.y;
                A2x += WD * p3.x; A2y += WD * p3.y;
            } else {
                A1x += WT2 * p3.x; A1y += WT2 * p3.y;
                A2x += WT6 * p3.x; A2y += WT6 * p3.y;
                A3x += WT5 * p3.x; A3y += WT5 * p3.y;
                A4x += WT1 * p3.x; A4y += WT1 * p3.y;
            }
        }
        if (kk >= 4) {                         // output row kk-4 complete
            float2 v; v.x = A0x; v.y = A0y;
            reinterpret_cast<float2*>(vrows + (kk - 4) * HW)[t] = v;
        }
        A0x = A1x; A0y = A1y; A1x = A2x; A1y = A2y;
        A2x = A3x; A2y = A3y; A3x = A4x; A3y = A4y;
        A4x = 0.f; A4y = 0.f;
    }
}

__global__ __launch_bounds__(THREADS, 5)
void assr_fused_kernel(const float* __restrict__ pred,
                       const float* __restrict__ tgt,
                       const float* __restrict__ lrr,
                       float* __restrict__ out, int out_size)
{
    __shared__ float  vrows[CHAIN * HW];   // 32 KB vertical-result buffer
    __shared__ float  red[16];
    __shared__ double dred[16];
    __shared__ unsigned sh_last;

    const int t   = threadIdx.x;           // owns columns 2t, 2t+1
    const int s   = blockIdx.x;             // 0..7
    const int bc  = blockIdx.y;             // 0..95
    const int oh0 = CHAIN * s;

    const float2* P2 = reinterpret_cast<const float2*>(pred + (size_t)bc * (HW * HW)) + t;
    const float2* T2 = reinterpret_cast<const float2*>(tgt  + (size_t)bc * (HW * HW)) + t;

    float pixs = 0.f, lrs = 0.f;

    if (s == 0)                vert_pass<true , false>(P2, T2, oh0, t, vrows, pixs);
    else if (s == SPLITS - 1)  vert_pass<false, true >(P2, T2, oh0, t, vrows, pixs);
    else                       vert_pass<false, false>(P2, T2, oh0, t, vrows, pixs);
    __syncthreads();

    // ---------------- horizontal FIR from smem + lr reduction --------------
    const int ow = t & (OUTHW - 1);
    const int r0 = t >> 7;                  // 0..1; rows r0, r0+2, ..., r0+14
    const float* lrbase = lrr + (size_t)bc * (OUTHW * OUTHW)
                              + (size_t)oh0 * OUTHW + ow;

    if (ow >= 2 && ow < OUTHW - 2) {
        // interior: 5 aligned, conflict-free LDS.128 per output
        #pragma unroll
        for (int i = 0; i < CHAIN / 2; ++i) {
            const int rr = r0 + 2 * i;
            const float4* v =
                reinterpret_cast<const float4*>(vrows + rr * HW) + (ow - 2);
            const float4 a = v[0], b = v[1], c = v[2], d = v[3], e = v[4];
            float acc = a.z * WT0 + a.w * WT1
                      + b.x * WT2 + b.y * WT3 + b.z * WT4 + b.w * WT5
                      + c.x * WT6 + c.y * WT7 + c.z * WT7 + c.w * WT6
                      + d.x * WT5 + d.y * WT4 + d.z * WT3 + d.w * WT2
                      + e.x * WT1 + e.y * WT0;
            lrs += fabsf(acc - lrbase[rr * OUTHW]);
        }
    } else {
        // border ow in {0,1,126,127}: scalar clamped gather (replicate fold)
        for (int i = 0; i < CHAIN / 2; ++i) {
            const int rr = r0 + 2 * i;
            const float* row = vrows + rr * HW;
            float acc = 0.f;
            #pragma unroll
            for (int tt = 0; tt < 16; ++tt) {
                int src = 4 * ow - 6 + tt;
                src = src < 0 ? 0 : (src > HW - 1 ? HW - 1 : src);
                acc += c_wt[tt] * row[src];
            }
            lrs += fabsf(acc - lrbase[rr * OUTHW]);
        }
    }

    // ---------------- block reduction -> per-block partial slot ------------
    #pragma unroll
    for (int o = 16; o; o >>= 1) {
        pixs += __shfl_xor_sync(0xffffffffu, pixs, o);
        lrs  += __shfl_xor_sync(0xffffffffu, lrs,  o);
    }
    const int wid = t >> 5, lane = t & 31;
    if (lane == 0) { red[wid] = pixs; red[8 + wid] = lrs; }
    __syncthreads();
    if (t == 0) {
        double ps = 0.0, ls = 0.0;
        #pragma unroll
        for (int i = 0; i < THREADS / 32; ++i) {
            ps += (double)red[i];
            ls += (double)red[8 + i];
        }
        const int slot = bc * SPLITS + s;
        g_pp[slot] = ps;
        g_pl[slot] = ls;
        __threadfence();
        const unsigned old = atomicAdd(&g_count, 1u);
        sh_last = (old == NBLOCKS - 1) ? 1u : 0u;
    }
    __syncthreads();

    // ---------------- last block finalizes ---------------------------------
    if (sh_last) {
        double p = 0.0, l = 0.0;
        #pragma unroll
        for (int i = 0; i < NBLOCKS / THREADS; ++i) {   // 3 slots per thread
            p += __ldcg(&g_pp[t + THREADS * i]);
            l += __ldcg(&g_pl[t + THREADS * i]);
        }
        #pragma unroll
        for (int o = 16; o; o >>= 1) {
            p += __shfl_xor_sync(0xffffffffu, p, o);
            l += __shfl_xor_sync(0xffffffffu, l, o);
        }
        if (lane == 0) { dred[wid] = p; dred[8 + wid] = l; }
        __syncthreads();
        if (t == 0) {
            double ps = 0.0, ls = 0.0;
            #pragma unroll
            for (int i = 0; i < THREADS / 32; ++i) {
                ps += dred[i];
                ls += dred[8 + i];
            }
            const double pix     = ps / 25165824.0;   // 32*3*512*512
            const double lr      = ls / 1572864.0;    // 32*3*128*128
            const double consist = lr;                 // LAM_LR*lr + 0
            const double total   = pix + 0.1 * consist;
            float vals[5] = {(float)total, (float)pix, (float)consist,
                             (float)lr, 0.f};
            for (int i = 0; i < out_size; ++i)
                out[i] = (i < 5) ? vals[i] : 0.f;
            g_count = 0;           // reset for next launch (deterministic)
        }
    }
}

extern "C" void kernel_launch(void* const* d_in, const int* in_sizes, int n_in,
                              void* d_out, int out_size)
{
    const float* pred = (const float*)d_in[0];
    const float* tgt  = (const float*)d_in[1];
    const float* lrr  = (const float*)d_in[2];
    // d_in[3] (scale) is uniform 4.0 -> static sizes, unused.

    const dim3 grid(SPLITS, NBC);
    assr_fused_kernel<<<grid, THREADS>>>(pred, tgt, lrr,
                                         (float*)d_out, out_size);
}